// round 10
// baseline (speedup 1.0000x reference)
#include <cuda_runtime.h>
#include <cuda_fp16.h>
#include <math.h>

#define BB 2
#define LL 2048
#define SS 2048
#define HH 16
#define EE 64
#define TQ 64
#define TK 64
#define PITCH 144  // smem row pitch: 64 fp16 (128B) + 16B pad

#define NELEM (BB * HH * LL * EE)

__device__ __align__(16) __half gQ[NELEM];
__device__ __align__(16) __half gK[NELEM];
__device__ __align__(16) __half gV[NELEM];

// ---------------- helpers ----------------
__device__ __forceinline__ unsigned smem_u32(const void* p) {
    unsigned a;
    asm("{ .reg .u64 t; cvta.to.shared.u64 t, %1; cvt.u32.u64 %0, t; }"
        : "=r"(a) : "l"(p));
    return a;
}
#define CP16(dst, src) \
    asm volatile("cp.async.cg.shared.global [%0], [%1], 16;" :: "r"(dst), "l"(src))
#define CP_COMMIT() asm volatile("cp.async.commit_group;" ::: "memory")
#define CP_WAIT0()  asm volatile("cp.async.wait_group 0;" ::: "memory")
#define CP_WAIT2()  asm volatile("cp.async.wait_group 2;" ::: "memory")

__device__ __forceinline__ void ldsm4(unsigned r[4], unsigned addr) {
    asm volatile("ldmatrix.sync.aligned.m8n8.x4.shared.b16 {%0,%1,%2,%3}, [%4];"
                 : "=r"(r[0]), "=r"(r[1]), "=r"(r[2]), "=r"(r[3]) : "r"(addr));
}
__device__ __forceinline__ void ldsm4t(unsigned r[4], unsigned addr) {
    asm volatile("ldmatrix.sync.aligned.m8n8.x4.trans.shared.b16 {%0,%1,%2,%3}, [%4];"
                 : "=r"(r[0]), "=r"(r[1]), "=r"(r[2]), "=r"(r[3]) : "r"(addr));
}
__device__ __forceinline__ void mma16816(float* c, const unsigned a[4],
                                         unsigned b0, unsigned b1) {
    asm volatile(
        "mma.sync.aligned.m16n8k16.row.col.f32.f16.f16.f32 "
        "{%0,%1,%2,%3}, {%4,%5,%6,%7}, {%8,%9}, {%0,%1,%2,%3};"
        : "+f"(c[0]), "+f"(c[1]), "+f"(c[2]), "+f"(c[3])
        : "r"(a[0]), "r"(a[1]), "r"(a[2]), "r"(a[3]), "r"(b0), "r"(b1));
}
__device__ __forceinline__ unsigned pack2h(float lo, float hi) {
    __half2 p = __floats2half2_rn(lo, hi);
    return *reinterpret_cast<unsigned*>(&p);
}
__device__ __forceinline__ float ex2(float x) {
    float r;
    asm("ex2.approx.ftz.f32 %0, %1;" : "=f"(r) : "f"(x));
    return r;
}
#define STS32(addr, v) \
    asm volatile("st.shared.u32 [%0], %1;" :: "r"(addr), "r"(v) : "memory")

// ---------------------------------------------------------------------------
// Prep: fp32 [b,s,h,e] -> fp16 [b,h,s,e]; Q scaled by 0.125*log2(e).
// ---------------------------------------------------------------------------
__global__ __launch_bounds__(256)
void prep(const float* __restrict__ Q, const float* __restrict__ K,
          const float* __restrict__ V) {
    const unsigned per = NELEM / 4;
    unsigned idx = blockIdx.x * 256u + threadIdx.x;
    if (idx >= 3u * per) return;
    const int t = idx / per;
    const unsigned c = idx % per;

    const unsigned e4 = c & 15;
    const unsigned r  = c >> 4;
    const unsigned h  = r & (HH - 1);
    const unsigned bs = r >> 4;
    const unsigned s  = bs & (LL - 1);
    const unsigned b  = bs >> 11;

    const float* src = (t == 0) ? Q : (t == 1) ? K : V;
    float4 v = *(const float4*)(src + (size_t)c * 4);
    if (t == 0) {
        const float sc = 0.18033688011112042f;  // 0.125 * log2(e)
        v.x *= sc; v.y *= sc; v.z *= sc; v.w *= sc;
    }
    __half* oh = (t == 0) ? gQ : (t == 1) ? gK : gV;
    const size_t o = (((size_t)(b * HH + h) * LL + s) * EE) + e4 * 4;
    *(uint2*)(oh + o) = make_uint2(pack2h(v.x, v.y), pack2h(v.z, v.w));
}

// ---------------------------------------------------------------------------
// Fused attention. TQ=64, 8 warps.
// QK phase: warp (wr 0..3 = 16 rows, wc 0..1 = 32 cols).
// PV phase: warp (r2 = 32 rows, d2 = 32 d-cols, j2 = 32 j-half); P staged in
// smem fp16; O partials reduced over j2 pairs once at the end.
// ---------------------------------------------------------------------------
__global__ __launch_bounds__(256, 3)
void attn_tc(float* __restrict__ Aout, float* __restrict__ Vout) {
    extern __shared__ char sm[];
    const unsigned uS = smem_u32(sm);
    const unsigned uQ = uS;                        // 9216
#define BUF(i) (uS + 9216u + (unsigned)(i) * 9216u)   // 4 slots
    const unsigned uP = uS + 46080u;               // P stage: 64 x PITCH = 9216
    const unsigned uR = uS + 55296u;               // rowsum halves: 2 x 64 floats

    const int tid  = threadIdx.x;
    const int lane = tid & 31;
    const int w    = tid >> 5;       // 0..7
    const int wr   = w >> 1;         // QK row group
    const int wc   = w & 1;          // QK col half
    const int r2   = w >> 2;         // PV row half
    const int d2   = (w >> 1) & 1;   // PV d half
    const int j2   = w & 1;          // PV j half

    const int g    = lane >> 2;
    const int tig  = lane & 3;

    const int bh = blockIdx.y;
    const int b  = bh / HH, h = bh % HH;
    const int qt = (int)gridDim.x - 1 - (int)blockIdx.x;  // heavy tiles first
    const int q0 = qt * TQ;

    const size_t qbase  = ((size_t)bh * LL + q0) * EE;
    const size_t kvbase = (size_t)bh * LL * EE;
    const int nkt = qt + 1;

    // ---- issue Q tile; pre-issue K0..K2 as 3 groups ----
    for (int c = tid; c < 512; c += 256) {
        const int i = c >> 3, ch = c & 7;
        CP16(uQ + i * PITCH + ch * 16, gQ + qbase + (size_t)i * EE + ch * 8);
    }
    for (int p = 0; p < 3; ++p) {
        if (p < nkt) {
            const size_t rb = kvbase + (size_t)p * TK * EE;
            for (int c = tid; c < 512; c += 256) {
                const int i = c >> 3, ch = c & 7;
                CP16(BUF(p) + i * PITCH + ch * 16, gK + rb + (size_t)i * EE + ch * 8);
            }
        }
        CP_COMMIT();
    }

    const int lr  = (lane & 7) + ((lane >> 3) & 1) * 8;
    const int lco = (lane >> 4) * 8;
    const unsigned qrow = (unsigned)((wr * 16 + lr) * PITCH + lco * 2);
    const unsigned krow = (unsigned)(lr * PITCH + lco * 2);

    const int gi0 = q0 + wr * 16 + g;
    const int gi1 = gi0 + 8;
    const int colbase = wc * 32;

    float rsum0 = 0.0f, rsum1 = 0.0f;
    unsigned qp[4][4];  // persistent Q frags (sweep 1)

    // ================= sweep 1: row sums (K ring of 4, distance 3) ==========
    for (int kt = 0; kt < nkt; ++kt) {
        CP_WAIT2();
        __syncthreads();
        if (kt == 0) {
#pragma unroll
            for (int ks = 0; ks < 4; ++ks) ldsm4(qp[ks], uQ + qrow + ks * 32);
        }
        if (kt + 3 < nkt) {
            const size_t rb = kvbase + (size_t)(kt + 3) * TK * EE;
            const unsigned uN = BUF((kt + 3) & 3);
            for (int c = tid; c < 512; c += 256) {
                const int i = c >> 3, ch = c & 7;
                CP16(uN + i * PITCH + ch * 16, gK + rb + (size_t)i * EE + ch * 8);
            }
        }
        CP_COMMIT();
        const unsigned uK = BUF(kt & 3);

        float s[4][4];
#pragma unroll
        for (int nb = 0; nb < 4; ++nb)
#pragma unroll
            for (int c = 0; c < 4; ++c) s[nb][c] = 0.0f;
#pragma unroll
        for (int ks = 0; ks < 4; ++ks) {
#pragma unroll
            for (int jg = 0; jg < 2; ++jg) {
                unsigned kf[4];
                ldsm4(kf, uK + (colbase + jg * 16) * PITCH + krow + ks * 32);
                mma16816(s[2 * jg],     qp[ks], kf[0], kf[2]);
                mma16816(s[2 * jg + 1], qp[ks], kf[1], kf[3]);
            }
        }
        const int k0 = kt * TK;
        const bool anymask = (k0 + colbase + 32 > gi0);
#pragma unroll
        for (int nb = 0; nb < 4; ++nb) {
            const int cj = k0 + colbase + nb * 8 + 2 * tig;
            float e0 = ex2(s[nb][0]);
            float e1 = ex2(s[nb][1]);
            float e2 = ex2(s[nb][2]);
            float e3 = ex2(s[nb][3]);
            if (anymask) {
                if (cj     > gi0) e0 = 0.0f;
                if (cj + 1 > gi0) e1 = 0.0f;
                if (cj     > gi1) e2 = 0.0f;
                if (cj + 1 > gi1) e3 = 0.0f;
            }
            rsum0 += e0 + e1;
            rsum1 += e2 + e3;
        }
    }

    rsum0 += __shfl_xor_sync(0xffffffffu, rsum0, 1);
    rsum0 += __shfl_xor_sync(0xffffffffu, rsum0, 2);
    rsum1 += __shfl_xor_sync(0xffffffffu, rsum1, 1);
    rsum1 += __shfl_xor_sync(0xffffffffu, rsum1, 2);
    if (tig == 0) {
        *(float*)(sm + (uR - uS) + (wc * 64 + wr * 16 + g) * 4)     = rsum0;
        *(float*)(sm + (uR - uS) + (wc * 64 + wr * 16 + g + 8) * 4) = rsum1;
    }
    CP_WAIT0();
    __syncthreads();
    const float inv0 = 1.0f / (*(float*)(sm + (uR - uS) + (wr * 16 + g) * 4) +
                               *(float*)(sm + (uR - uS) + (64 + wr * 16 + g) * 4));
    const float inv1 = 1.0f / (*(float*)(sm + (uR - uS) + (wr * 16 + g + 8) * 4) +
                               *(float*)(sm + (uR - uS) + (64 + wr * 16 + g + 8) * 4));

    // ---- issue K0 (BUF0) + V0 (BUF2) for sweep 2, then zero-fill ----
    for (int c = tid; c < 1024; c += 256) {
        const int arr = c >> 9, i = (c >> 3) & 63, ch = c & 7;
        const __half* gsrc = arr ? gV : gK;
        const unsigned dst = arr ? BUF(2) : BUF(0);
        CP16(dst + i * PITCH + ch * 16, gsrc + kvbase + (size_t)i * EE + ch * 8);
    }
    CP_COMMIT();

    if (Aout) {
        const int c0 = q0 + TQ;
        const int w4 = (SS - c0) >> 2;
        if (w4 > 0) {
            const float4 z = make_float4(0.f, 0.f, 0.f, 0.f);
            float* Abase = Aout + ((size_t)bh * LL + q0) * SS + c0;
            for (int i = tid; i < TQ * w4; i += 256) {
                const int r = i / w4;
                const int c = i - r * w4;
                __stcs((float4*)(Abase + (size_t)r * SS + 4 * c), z);
            }
        }
    }

    float o[2][4][4];  // [rowblock][n8 over 32 d][frag]
#pragma unroll
    for (int rb = 0; rb < 2; ++rb)
#pragma unroll
        for (int nb = 0; nb < 4; ++nb)
#pragma unroll
            for (int c = 0; c < 4; ++c) o[rb][nb][c] = 0.0f;

    // ================= sweep 2: normalized A + O =================
    for (int kt = 0; kt < nkt; ++kt) {
        const int k0 = kt * TK;
        CP_WAIT0();
        __syncthreads();
        if (kt + 1 < nkt) {
            const unsigned nb1 = (kt + 1) & 1;
            const size_t rb = kvbase + (size_t)(kt + 1) * TK * EE;
            for (int c = tid; c < 1024; c += 256) {
                const int arr = c >> 9, i = (c >> 3) & 63, ch = c & 7;
                const __half* gsrc = arr ? gV : gK;
                const unsigned base = arr ? BUF(2 + nb1) : BUF(nb1);
                CP16(base + i * PITCH + ch * 16, gsrc + rb + (size_t)i * EE + ch * 8);
            }
        }
        CP_COMMIT();
        const unsigned uK = BUF(kt & 1);
        const unsigned uV = BUF(2 + (kt & 1));

        // ---- QK ----
        float s[4][4];
#pragma unroll
        for (int nb = 0; nb < 4; ++nb)
#pragma unroll
            for (int c = 0; c < 4; ++c) s[nb][c] = 0.0f;
#pragma unroll
        for (int ks = 0; ks < 4; ++ks) {
            unsigned qf[4];
            ldsm4(qf, uQ + qrow + ks * 32);
#pragma unroll
            for (int jg = 0; jg < 2; ++jg) {
                unsigned kf[4];
                ldsm4(kf, uK + (colbase + jg * 16) * PITCH + krow + ks * 32);
                mma16816(s[2 * jg],     qf, kf[0], kf[2]);
                mma16816(s[2 * jg + 1], qf, kf[1], kf[3]);
            }
        }

        // ---- epilogue: normalize, store A, stage P fp16 in smem ----
        const bool anymask = (k0 + colbase + 32 > gi0);
        float* A0 = Aout ? (Aout + ((size_t)bh * LL + gi0) * SS + k0 + colbase) : (float*)0;
        float* A1 = Aout ? (Aout + ((size_t)bh * LL + gi1) * SS + k0 + colbase) : (float*)0;
#pragma unroll
        for (int nb = 0; nb < 4; ++nb) {
            const int cj = k0 + colbase + nb * 8 + 2 * tig;
            float e0 = ex2(s[nb][0]);
            float e1 = ex2(s[nb][1]);
            float e2 = ex2(s[nb][2]);
            float e3 = ex2(s[nb][3]);
            if (anymask) {
                if (cj     > gi0) e0 = 0.0f;
                if (cj + 1 > gi0) e1 = 0.0f;
                if (cj     > gi1) e2 = 0.0f;
                if (cj + 1 > gi1) e3 = 0.0f;
            }
            e0 *= inv0; e1 *= inv0; e2 *= inv1; e3 *= inv1;
            if (A0) {
                __stcs((float2*)(A0 + nb * 8 + 2 * tig), make_float2(e0, e1));
                __stcs((float2*)(A1 + nb * 8 + 2 * tig), make_float2(e2, e3));
            }
            const unsigned pcol = (unsigned)(colbase + nb * 8 + 2 * tig) * 2u;
            STS32(uP + (wr * 16 + g) * PITCH + pcol,     pack2h(e0, e1));
            STS32(uP + (wr * 16 + g + 8) * PITCH + pcol, pack2h(e2, e3));
        }
        __syncthreads();  // P stage complete

        // ---- PV: warp (r2, d2, j2) ----
#pragma unroll
        for (int kc = 0; kc < 2; ++kc) {
            const int jb = j2 * 32 + kc * 16;
            unsigned pa0[4], pa1[4];
            ldsm4(pa0, uP + (r2 * 32 + lr) * PITCH + (jb + lco) * 2);
            ldsm4(pa1, uP + (r2 * 32 + 16 + lr) * PITCH + (jb + lco) * 2);
#pragma unroll
            for (int dd = 0; dd < 2; ++dd) {
                unsigned vf[4];
                ldsm4t(vf, uV + (jb + lr) * PITCH + lco * 2 + (d2 * 32 + dd * 16) * 2);
                mma16816(o[0][2 * dd],     pa0, vf[0], vf[1]);
                mma16816(o[0][2 * dd + 1], pa0, vf[2], vf[3]);
                mma16816(o[1][2 * dd],     pa1, vf[0], vf[1]);
                mma16816(o[1][2 * dd + 1], pa1, vf[2], vf[3]);
            }
        }
    }

    // ---- O: reduce j2 partials across warp pairs, write out ----
    if (Vout) {
        __syncthreads();  // all PV reads of P/V done; K slots reusable
        const unsigned uOst = BUF(0) + (unsigned)(r2 * 2 + d2) * 4608u;
        if (j2 == 1) {
#pragma unroll
            for (int rb = 0; rb < 2; ++rb)
#pragma unroll
                for (int nb = 0; nb < 4; ++nb) {
                    *(float2*)(sm + (uOst - uS) + ((rb * 16 + g) * 36 + nb * 8 + 2 * tig) * 4) =
                        make_float2(o[rb][nb][0], o[rb][nb][1]);
                    *(float2*)(sm + (uOst - uS) + ((rb * 16 + g + 8) * 36 + nb * 8 + 2 * tig) * 4) =
                        make_float2(o[rb][nb][2], o[rb][nb][3]);
                }
        }
        __syncthreads();
        if (j2 == 0) {
#pragma unroll
            for (int rb = 0; rb < 2; ++rb) {
                const int gr0 = q0 + r2 * 32 + rb * 16 + g;
                float* O0 = Vout + (((size_t)(b * LL + gr0) * HH + h) * EE) + d2 * 32;
                float* O1 = O0 + (size_t)8 * HH * EE;
#pragma unroll
                for (int nb = 0; nb < 4; ++nb) {
                    float2 p0 = *(float2*)(sm + (uOst - uS) + ((rb * 16 + g) * 36 + nb * 8 + 2 * tig) * 4);
                    float2 p1 = *(float2*)(sm + (uOst - uS) + ((rb * 16 + g + 8) * 36 + nb * 8 + 2 * tig) * 4);
                    *(float2*)(O0 + nb * 8 + 2 * tig) =
                        make_float2(o[rb][nb][0] + p0.x, o[rb][nb][1] + p0.y);
                    *(float2*)(O1 + nb * 8 + 2 * tig) =
                        make_float2(o[rb][nb][2] + p1.x, o[rb][nb][3] + p1.y);
                }
            }
        }
    }
#undef BUF
}

// ---------------------------------------------------------------------------
extern "C" void kernel_launch(void* const* d_in, const int* in_sizes, int n_in,
                              void* d_out, int out_size) {
    const float* Q = (const float*)d_in[0];
    const float* K = (const float*)d_in[1];
    const float* V = (const float*)d_in[2];

    const int V_SIZE = BB * LL * HH * EE;
    const int A_SIZE = (int)((size_t)BB * HH * LL * SS);

    float* out  = (float*)d_out;
    float* Vout = 0;
    float* Aout = 0;
    if (out_size >= V_SIZE + A_SIZE) { Vout = out; Aout = out + V_SIZE; }
    else if (out_size == A_SIZE)     { Aout = out; }
    else                             { Vout = out; }

    const unsigned prep_total = 3u * (NELEM / 4);
    prep<<<(prep_total + 255u) / 256u, 256>>>(Q, K, V);

    const int smem = 55808;
    cudaFuncSetAttribute(attn_tc, cudaFuncAttributeMaxDynamicSharedMemorySize, smem);
    dim3 grid1(LL / TQ, BB * HH);
    attn_tc<<<grid1, 256, smem>>>(Aout, Vout);
}

// round 12
// speedup vs baseline: 1.0272x; 1.0272x over previous
#include <cuda_runtime.h>
#include <cuda_fp16.h>
#include <math.h>

#define BB 2
#define LL 2048
#define SS 2048
#define HH 16
#define EE 64
#define TQ 64
#define TK 64
#define PITCH 144   // K/V/Q smem row pitch
#define PPITCH 144  // P staging pitch: 16B-aligned, 4-bank row stagger

#define NELEM (BB * HH * LL * EE)

__device__ __align__(16) __half gQ[NELEM];
__device__ __align__(16) __half gK[NELEM];
__device__ __align__(16) __half gV[NELEM];

// ---------------- helpers ----------------
__device__ __forceinline__ unsigned smem_u32(const void* p) {
    unsigned a;
    asm("{ .reg .u64 t; cvta.to.shared.u64 t, %1; cvt.u32.u64 %0, t; }"
        : "=r"(a) : "l"(p));
    return a;
}
#define CP16(dst, src) \
    asm volatile("cp.async.cg.shared.global [%0], [%1], 16;" :: "r"(dst), "l"(src))
#define CP_COMMIT() asm volatile("cp.async.commit_group;" ::: "memory")
#define CP_WAIT0()  asm volatile("cp.async.wait_group 0;" ::: "memory")

__device__ __forceinline__ void ldsm4(unsigned r[4], unsigned addr) {
    asm volatile("ldmatrix.sync.aligned.m8n8.x4.shared.b16 {%0,%1,%2,%3}, [%4];"
                 : "=r"(r[0]), "=r"(r[1]), "=r"(r[2]), "=r"(r[3]) : "r"(addr));
}
__device__ __forceinline__ void ldsm4t(unsigned r[4], unsigned addr) {
    asm volatile("ldmatrix.sync.aligned.m8n8.x4.trans.shared.b16 {%0,%1,%2,%3}, [%4];"
                 : "=r"(r[0]), "=r"(r[1]), "=r"(r[2]), "=r"(r[3]) : "r"(addr));
}
__device__ __forceinline__ void mma16816(float* c, const unsigned a[4],
                                         unsigned b0, unsigned b1) {
    asm volatile(
        "mma.sync.aligned.m16n8k16.row.col.f32.f16.f16.f32 "
        "{%0,%1,%2,%3}, {%4,%5,%6,%7}, {%8,%9}, {%0,%1,%2,%3};"
        : "+f"(c[0]), "+f"(c[1]), "+f"(c[2]), "+f"(c[3])
        : "r"(a[0]), "r"(a[1]), "r"(a[2]), "r"(a[3]), "r"(b0), "r"(b1));
}
__device__ __forceinline__ unsigned pack2h(float lo, float hi) {
    __half2 p = __floats2half2_rn(lo, hi);
    return *reinterpret_cast<unsigned*>(&p);
}
__device__ __forceinline__ float ex2(float x) {
    float r;
    asm("ex2.approx.ftz.f32 %0, %1;" : "=f"(r) : "f"(x));
    return r;
}
#define STS32(addr, v) \
    asm volatile("st.shared.u32 [%0], %1;" :: "r"(addr), "r"(v) : "memory")

// ---------------------------------------------------------------------------
// Prep: fp32 [b,s,h,e] -> fp16 [b,h,s,e]; Q scaled by 0.125*log2(e).
// ---------------------------------------------------------------------------
__global__ __launch_bounds__(256)
void prep(const float* __restrict__ Q, const float* __restrict__ K,
          const float* __restrict__ V) {
    const unsigned per = NELEM / 4;
    unsigned idx = blockIdx.x * 256u + threadIdx.x;
    if (idx >= 3u * per) return;
    const int t = idx / per;
    const unsigned c = idx % per;

    const unsigned e4 = c & 15;
    const unsigned r  = c >> 4;
    const unsigned h  = r & (HH - 1);
    const unsigned bs = r >> 4;
    const unsigned s  = bs & (LL - 1);
    const unsigned b  = bs >> 11;

    const float* src = (t == 0) ? Q : (t == 1) ? K : V;
    float4 v = *(const float4*)(src + (size_t)c * 4);
    if (t == 0) {
        const float sc = 0.18033688011112042f;  // 0.125 * log2(e)
        v.x *= sc; v.y *= sc; v.z *= sc; v.w *= sc;
    }
    __half* oh = (t == 0) ? gQ : (t == 1) ? gK : gV;
    const size_t o = (((size_t)(b * HH + h) * LL + s) * EE) + e4 * 4;
    *(uint2*)(oh + o) = make_uint2(pack2h(v.x, v.y), pack2h(v.z, v.w));
}

// ---------------------------------------------------------------------------
// Fused attention (R8 structure). TQ=64, 4 warps, 4 CTAs/SM.
// Sweep 1: exact row sums. Sweep 2: recompute S, write normalized A + O.
// A writeback: stage normalized P fp16 in smem -> coalesced STG.128.
// ---------------------------------------------------------------------------
__global__ __launch_bounds__(128, 4)
void attn_tc(float* __restrict__ Aout, float* __restrict__ Vout) {
    extern __shared__ char sm[];
    const unsigned uS  = smem_u32(sm);
    const unsigned uQ  = uS;                 // 64 rows x PITCH = 9216
    const unsigned uKB = uS + 9216;          // 2 bufs x 9216
    const unsigned uVB = uS + 27648;         // 2 bufs x 9216
    const unsigned uP  = uS + 46080;         // P stage: 64 x PPITCH = 9216

    const int tid  = threadIdx.x;
    const int lane = tid & 31;
    const int w    = tid >> 5;        // 0..3
    const int g    = lane >> 2;
    const int tig  = lane & 3;

    const int bh = blockIdx.y;
    const int b  = bh / HH, h = bh % HH;
    const int qt = (int)gridDim.x - 1 - (int)blockIdx.x;  // heavy tiles first
    const int q0 = qt * TQ;

    const size_t qbase  = ((size_t)bh * LL + q0) * EE;
    const size_t kvbase = (size_t)bh * LL * EE;
    const int nkt = qt + 1;

    // ---- issue Q tile + K tile 0 ----
    for (int c = tid; c < 512; c += 128) {
        const int i = c >> 3, ch = c & 7;
        CP16(uQ + i * PITCH + ch * 16, gQ + qbase + (size_t)i * EE + ch * 8);
    }
    for (int c = tid; c < 512; c += 128) {
        const int i = c >> 3, ch = c & 7;
        CP16(uKB + i * PITCH + ch * 16, gK + kvbase + (size_t)i * EE + ch * 8);
    }
    CP_COMMIT();

    const int lr  = (lane & 7) + ((lane >> 3) & 1) * 8;
    const int lco = (lane >> 4) * 8;
    const unsigned qrow = (unsigned)((w * 16 + lr) * PITCH + lco * 2);
    const unsigned krow = (unsigned)(lr * PITCH + lco * 2);

    const int gi0 = q0 + w * 16 + g;
    const int gi1 = gi0 + 8;

    float rsum0 = 0.0f, rsum1 = 0.0f;

    // ================= sweep 1: row sums only =================
    for (int kt = 0; kt < nkt; ++kt) {
        CP_WAIT0();
        __syncthreads();
        if (kt + 1 < nkt) {
            const unsigned uN = uKB + ((kt + 1) & 1) * 9216u;
            const size_t rb = kvbase + (size_t)(kt + 1) * TK * EE;
            for (int c = tid; c < 512; c += 128) {
                const int i = c >> 3, ch = c & 7;
                CP16(uN + i * PITCH + ch * 16, gK + rb + (size_t)i * EE + ch * 8);
            }
            CP_COMMIT();
        }
        const unsigned uK = uKB + (kt & 1) * 9216u;

        float s[8][4];
#pragma unroll
        for (int nb = 0; nb < 8; ++nb)
#pragma unroll
            for (int c = 0; c < 4; ++c) s[nb][c] = 0.0f;
#pragma unroll
        for (int ks = 0; ks < 4; ++ks) {
            unsigned qf[4];
            ldsm4(qf, uQ + qrow + ks * 32);
#pragma unroll
            for (int jg = 0; jg < 4; ++jg) {
                unsigned kf[4];
                ldsm4(kf, uK + jg * 16 * PITCH + krow + ks * 32);
                mma16816(s[2 * jg],     qf, kf[0], kf[2]);
                mma16816(s[2 * jg + 1], qf, kf[1], kf[3]);
            }
        }
        const int k0 = kt * TK;
        const bool anymask = (k0 + TK > gi0);
#pragma unroll
        for (int nb = 0; nb < 8; ++nb) {
            const int cj = k0 + nb * 8 + 2 * tig;
            float e0 = ex2(s[nb][0]);
            float e1 = ex2(s[nb][1]);
            float e2 = ex2(s[nb][2]);
            float e3 = ex2(s[nb][3]);
            if (anymask) {
                if (cj     > gi0) e0 = 0.0f;
                if (cj + 1 > gi0) e1 = 0.0f;
                if (cj     > gi1) e2 = 0.0f;
                if (cj + 1 > gi1) e3 = 0.0f;
            }
            rsum0 += e0 + e1;
            rsum1 += e2 + e3;
        }
    }

    rsum0 += __shfl_xor_sync(0xffffffffu, rsum0, 1);
    rsum0 += __shfl_xor_sync(0xffffffffu, rsum0, 2);
    rsum1 += __shfl_xor_sync(0xffffffffu, rsum1, 1);
    rsum1 += __shfl_xor_sync(0xffffffffu, rsum1, 2);
    const float inv0 = 1.0f / rsum0, inv1 = 1.0f / rsum1;

    // ---- issue K0+V0 for sweep 2, overlap zero-fill with loads ----
    __syncthreads();
    for (int c = tid; c < 1024; c += 128) {
        const int arr = c >> 9, i = (c >> 3) & 63, ch = c & 7;
        const __half* gsrc = arr ? gV : gK;
        const unsigned dst = arr ? uVB : uKB;
        CP16(dst + i * PITCH + ch * 16, gsrc + kvbase + (size_t)i * EE + ch * 8);
    }
    CP_COMMIT();

    if (Aout) {  // zero the strictly-upper rectangle of this q-strip
        const int c0 = q0 + TQ;
        const int w4 = (SS - c0) >> 2;
        if (w4 > 0) {
            const float4 z = make_float4(0.f, 0.f, 0.f, 0.f);
            float* Abase = Aout + ((size_t)bh * LL + q0) * SS + c0;
            for (int i = tid; i < TQ * w4; i += 128) {
                const int r = i / w4;
                const int c = i - r * w4;
                __stcs((float4*)(Abase + (size_t)r * SS + 4 * c), z);
            }
        }
    }

    float o[8][4];
#pragma unroll
    for (int nb = 0; nb < 8; ++nb)
#pragma unroll
        for (int c = 0; c < 4; ++c) o[nb][c] = 0.0f;

    // ================= sweep 2: normalized A + O =================
    for (int kt = 0; kt < nkt; ++kt) {
        const int k0 = kt * TK;
        CP_WAIT0();
        __syncthreads();  // buffers ready; prior A-writeback done -> uP reusable
        if (kt + 1 < nkt) {
            const unsigned nb1 = (kt + 1) & 1;
            const size_t rb = kvbase + (size_t)(kt + 1) * TK * EE;
            for (int c = tid; c < 1024; c += 128) {
                const int arr = c >> 9, i = (c >> 3) & 63, ch = c & 7;
                const __half* gsrc = arr ? gV : gK;
                const unsigned base = (arr ? uVB : uKB) + nb1 * 9216u;
                CP16(base + i * PITCH + ch * 16, gsrc + rb + (size_t)i * EE + ch * 8);
            }
            CP_COMMIT();
        }
        const unsigned uK = uKB + (kt & 1) * 9216u;
        const unsigned uV = uVB + (kt & 1) * 9216u;

        float s[8][4];
#pragma unroll
        for (int nb = 0; nb < 8; ++nb)
#pragma unroll
            for (int c = 0; c < 4; ++c) s[nb][c] = 0.0f;
#pragma unroll
        for (int ks = 0; ks < 4; ++ks) {
            unsigned qf[4];
            ldsm4(qf, uQ + qrow + ks * 32);
#pragma unroll
            for (int jg = 0; jg < 4; ++jg) {
                unsigned kf[4];
                ldsm4(kf, uK + jg * 16 * PITCH + krow + ks * 32);
                mma16816(s[2 * jg],     qf, kf[0], kf[2]);
                mma16816(s[2 * jg + 1], qf, kf[1], kf[3]);
            }
        }

        const bool anymask = (k0 + TK > gi0);
        const unsigned prow0 = uP + (unsigned)(w * 16 + g) * PPITCH;
        const unsigned prow1 = uP + (unsigned)(w * 16 + g + 8) * PPITCH;

#pragma unroll
        for (int ks = 0; ks < 4; ++ks) {
            unsigned ah[4];
#pragma unroll
            for (int half = 0; half < 2; ++half) {
                const int nb = 2 * ks + half;
                const int cj = k0 + nb * 8 + 2 * tig;
                float e0 = ex2(s[nb][0]);
                float e1 = ex2(s[nb][1]);
                float e2 = ex2(s[nb][2]);
                float e3 = ex2(s[nb][3]);
                if (anymask) {
                    if (cj     > gi0) e0 = 0.0f;
                    if (cj + 1 > gi0) e1 = 0.0f;
                    if (cj     > gi1) e2 = 0.0f;
                    if (cj + 1 > gi1) e3 = 0.0f;
                }
                e0 *= inv0; e1 *= inv0; e2 *= inv1; e3 *= inv1;
                const unsigned p0 = pack2h(e0, e1);
                const unsigned p1 = pack2h(e2, e3);
                ah[2 * half]     = p0;
                ah[2 * half + 1] = p1;
                const unsigned pcol = (unsigned)(nb * 8 + 2 * tig) * 2u;
                STS32(prow0 + pcol, p0);
                STS32(prow1 + pcol, p1);
            }
#pragma unroll
            for (int dg = 0; dg < 4; ++dg) {
                unsigned vf[4];
                ldsm4t(vf, uV + ks * 16 * PITCH + krow + dg * 32);
                mma16816(o[2 * dg],     ah, vf[0], vf[1]);
                mma16816(o[2 * dg + 1], ah, vf[2], vf[3]);
            }
        }

        // ---- coalesced A writeback from staged fp16 tile ----
        __syncthreads();  // P stage complete block-wide
        if (Aout) {
            float* Abase = Aout + ((size_t)bh * LL + q0) * SS + k0;
            for (int it = tid; it < 512; it += 128) {  // 64 rows x 8 chunks
                const int r = it >> 3, cc = it & 7;
                uint4 pk = *(uint4*)(sm + (uP - uS) + r * PPITCH + cc * 16);
                const __half2* hp = (const __half2*)&pk;
                float2 f0 = __half22float2(hp[0]);
                float2 f1 = __half22float2(hp[1]);
                float2 f2 = __half22float2(hp[2]);
                float2 f3 = __half22float2(hp[3]);
                float* dst = Abase + (size_t)r * SS + cc * 8;
                __stcs((float4*)dst,       make_float4(f0.x, f0.y, f1.x, f1.y));
                __stcs((float4*)(dst + 4), make_float4(f2.x, f2.y, f3.x, f3.y));
            }
        }
    }

    if (Vout) {
        float* O0 = Vout + (((size_t)(b * LL + gi0) * HH + h) * EE);
        float* O1 = Vout + (((size_t)(b * LL + gi1) * HH + h) * EE);
#pragma unroll
        for (int nb = 0; nb < 8; ++nb) {
            *(float2*)(O0 + nb * 8 + 2 * tig) = make_float2(o[nb][0], o[nb][1]);
            *(float2*)(O1 + nb * 8 + 2 * tig) = make_float2(o[nb][2], o[nb][3]);
        }
    }
}

// ---------------------------------------------------------------------------
extern "C" void kernel_launch(void* const* d_in, const int* in_sizes, int n_in,
                              void* d_out, int out_size) {
    const float* Q = (const float*)d_in[0];
    const float* K = (const float*)d_in[1];
    const float* V = (const float*)d_in[2];

    const int V_SIZE = BB * LL * HH * EE;
    const int A_SIZE = (int)((size_t)BB * HH * LL * SS);

    float* out  = (float*)d_out;
    float* Vout = 0;
    float* Aout = 0;
    if (out_size >= V_SIZE + A_SIZE) { Vout = out; Aout = out + V_SIZE; }
    else if (out_size == A_SIZE)     { Aout = out; }
    else                             { Vout = out; }

    const unsigned prep_total = 3u * (NELEM / 4);
    prep<<<(prep_total + 255u) / 256u, 256>>>(Q, K, V);

    const int smem = 55296;
    cudaFuncSetAttribute(attn_tc, cudaFuncAttributeMaxDynamicSharedMemorySize, smem);
    dim3 grid1(LL / TQ, BB * HH);
    attn_tc<<<grid1, 128, smem>>>(Aout, Vout);
}

// round 13
// speedup vs baseline: 1.0987x; 1.0697x over previous
#include <cuda_runtime.h>
#include <cuda_fp16.h>
#include <math.h>

#define BB 2
#define LL 2048
#define SS 2048
#define HH 16
#define EE 64
#define TQ 64
#define TK 64
#define PITCH 144  // smem row pitch: 64 fp16 (128B) + 16B pad

#define NELEM (BB * HH * LL * EE)

__device__ __align__(16) __half gQ[NELEM];
__device__ __align__(16) __half gK[NELEM];
__device__ __align__(16) __half gV[NELEM];

// ---------------- helpers ----------------
__device__ __forceinline__ unsigned smem_u32(const void* p) {
    unsigned a;
    asm("{ .reg .u64 t; cvta.to.shared.u64 t, %1; cvt.u32.u64 %0, t; }"
        : "=r"(a) : "l"(p));
    return a;
}
#define CP16(dst, src) \
    asm volatile("cp.async.cg.shared.global [%0], [%1], 16;" :: "r"(dst), "l"(src))
#define CP_COMMIT() asm volatile("cp.async.commit_group;" ::: "memory")
#define CP_WAIT0()  asm volatile("cp.async.wait_group 0;" ::: "memory")
#define CP_WAIT2()  asm volatile("cp.async.wait_group 2;" ::: "memory")

__device__ __forceinline__ void ldsm4(unsigned r[4], unsigned addr) {
    asm volatile("ldmatrix.sync.aligned.m8n8.x4.shared.b16 {%0,%1,%2,%3}, [%4];"
                 : "=r"(r[0]), "=r"(r[1]), "=r"(r[2]), "=r"(r[3]) : "r"(addr));
}
__device__ __forceinline__ void ldsm4t(unsigned r[4], unsigned addr) {
    asm volatile("ldmatrix.sync.aligned.m8n8.x4.trans.shared.b16 {%0,%1,%2,%3}, [%4];"
                 : "=r"(r[0]), "=r"(r[1]), "=r"(r[2]), "=r"(r[3]) : "r"(addr));
}
__device__ __forceinline__ void mma16816(float* c, const unsigned a[4],
                                         unsigned b0, unsigned b1) {
    asm volatile(
        "mma.sync.aligned.m16n8k16.row.col.f32.f16.f16.f32 "
        "{%0,%1,%2,%3}, {%4,%5,%6,%7}, {%8,%9}, {%0,%1,%2,%3};"
        : "+f"(c[0]), "+f"(c[1]), "+f"(c[2]), "+f"(c[3])
        : "r"(a[0]), "r"(a[1]), "r"(a[2]), "r"(a[3]), "r"(b0), "r"(b1));
}
__device__ __forceinline__ unsigned pack2h(float lo, float hi) {
    __half2 p = __floats2half2_rn(lo, hi);
    return *reinterpret_cast<unsigned*>(&p);
}
__device__ __forceinline__ float ex2(float x) {
    float r;
    asm("ex2.approx.ftz.f32 %0, %1;" : "=f"(r) : "f"(x));
    return r;
}
__device__ __forceinline__ float lg2(float x) {
    float r;
    asm("lg2.approx.ftz.f32 %0, %1;" : "=f"(r) : "f"(x));
    return r;
}

// ---------------------------------------------------------------------------
// Prep: fp32 [b,s,h,e] -> fp16 [b,h,s,e]; Q scaled by 0.125*log2(e).
// ---------------------------------------------------------------------------
__global__ __launch_bounds__(256)
void prep(const float* __restrict__ Q, const float* __restrict__ K,
          const float* __restrict__ V) {
    const unsigned per = NELEM / 4;
    unsigned idx = blockIdx.x * 256u + threadIdx.x;
    if (idx >= 3u * per) return;
    const int t = idx / per;
    const unsigned c = idx % per;

    const unsigned e4 = c & 15;
    const unsigned r  = c >> 4;
    const unsigned h  = r & (HH - 1);
    const unsigned bs = r >> 4;
    const unsigned s  = bs & (LL - 1);
    const unsigned b  = bs >> 11;

    const float* src = (t == 0) ? Q : (t == 1) ? K : V;
    float4 v = *(const float4*)(src + (size_t)c * 4);
    if (t == 0) {
        const float sc = 0.18033688011112042f;  // 0.125 * log2(e)
        v.x *= sc; v.y *= sc; v.z *= sc; v.w *= sc;
    }
    __half* oh = (t == 0) ? gQ : (t == 1) ? gK : gV;
    const size_t o = (((size_t)(b * HH + h) * LL + s) * EE) + e4 * 4;
    *(uint2*)(oh + o) = make_uint2(pack2h(v.x, v.y), pack2h(v.z, v.w));
}

// ---------------------------------------------------------------------------
// Fused attention. TQ=64, 4 warps, 4 CTAs/SM.
// Sweep 1: exact row sums with ring-4 K pipeline + persistent Q frags.
// Sweep 2: recompute S, normalize via exp2(s - log2(rsum)), write A + O.
// ---------------------------------------------------------------------------
__global__ __launch_bounds__(128, 4)
void attn_tc(float* __restrict__ Aout, float* __restrict__ Vout) {
    extern __shared__ char sm[];
    const unsigned uS = smem_u32(sm);
    const unsigned uQ = uS;                               // 9216
#define BUF(i) (uS + 9216u + (unsigned)(i) * 9216u)       // 4 ring slots

    const int tid  = threadIdx.x;
    const int lane = tid & 31;
    const int w    = tid >> 5;        // 0..3
    const int g    = lane >> 2;
    const int tig  = lane & 3;

    const int bh = blockIdx.y;
    const int b  = bh / HH, h = bh % HH;
    const int qt = (int)gridDim.x - 1 - (int)blockIdx.x;  // heavy tiles first
    const int q0 = qt * TQ;

    const size_t qbase  = ((size_t)bh * LL + q0) * EE;
    const size_t kvbase = (size_t)bh * LL * EE;
    const int nkt = qt + 1;

    // ---- issue Q tile; pre-issue K0..K2 as 3 groups ----
    for (int c = tid; c < 512; c += 128) {
        const int i = c >> 3, ch = c & 7;
        CP16(uQ + i * PITCH + ch * 16, gQ + qbase + (size_t)i * EE + ch * 8);
    }
    for (int p = 0; p < 3; ++p) {
        if (p < nkt) {
            const size_t rb = kvbase + (size_t)p * TK * EE;
            for (int c = tid; c < 512; c += 128) {
                const int i = c >> 3, ch = c & 7;
                CP16(BUF(p) + i * PITCH + ch * 16, gK + rb + (size_t)i * EE + ch * 8);
            }
        }
        CP_COMMIT();
    }

    const int lr  = (lane & 7) + ((lane >> 3) & 1) * 8;
    const int lco = (lane >> 4) * 8;
    const unsigned qrow = (unsigned)((w * 16 + lr) * PITCH + lco * 2);
    const unsigned krow = (unsigned)(lr * PITCH + lco * 2);

    const int gi0 = q0 + w * 16 + g;
    const int gi1 = gi0 + 8;

    float rsum0 = 0.0f, rsum1 = 0.0f;
    unsigned qp[4][4];  // persistent Q frags (sweep 1)

    // ================= sweep 1: row sums (K ring of 4, distance 3) ==========
    for (int kt = 0; kt < nkt; ++kt) {
        CP_WAIT2();           // exactly K(kt) (and older) guaranteed complete
        __syncthreads();
        if (kt == 0) {
#pragma unroll
            for (int ks = 0; ks < 4; ++ks) ldsm4(qp[ks], uQ + qrow + ks * 32);
        }
        if (kt + 3 < nkt) {   // issue K(kt+3) into slot freed at kt-1
            const size_t rb = kvbase + (size_t)(kt + 3) * TK * EE;
            const unsigned uN = BUF((kt + 3) & 3);
            for (int c = tid; c < 512; c += 128) {
                const int i = c >> 3, ch = c & 7;
                CP16(uN + i * PITCH + ch * 16, gK + rb + (size_t)i * EE + ch * 8);
            }
        }
        CP_COMMIT();
        const unsigned uK = BUF(kt & 3);

        float s[8][4];
#pragma unroll
        for (int nb = 0; nb < 8; ++nb)
#pragma unroll
            for (int c = 0; c < 4; ++c) s[nb][c] = 0.0f;
#pragma unroll
        for (int ks = 0; ks < 4; ++ks) {
#pragma unroll
            for (int jg = 0; jg < 4; ++jg) {
                unsigned kf[4];
                ldsm4(kf, uK + jg * 16 * PITCH + krow + ks * 32);
                mma16816(s[2 * jg],     qp[ks], kf[0], kf[2]);
                mma16816(s[2 * jg + 1], qp[ks], kf[1], kf[3]);
            }
        }
        const int k0 = kt * TK;
        const bool anymask = (k0 + TK > gi0);
#pragma unroll
        for (int nb = 0; nb < 8; ++nb) {
            const int cj = k0 + nb * 8 + 2 * tig;
            float e0 = ex2(s[nb][0]);
            float e1 = ex2(s[nb][1]);
            float e2 = ex2(s[nb][2]);
            float e3 = ex2(s[nb][3]);
            if (anymask) {
                if (cj     > gi0) e0 = 0.0f;
                if (cj + 1 > gi0) e1 = 0.0f;
                if (cj     > gi1) e2 = 0.0f;
                if (cj + 1 > gi1) e3 = 0.0f;
            }
            rsum0 += e0 + e1;
            rsum1 += e2 + e3;
        }
    }

    rsum0 += __shfl_xor_sync(0xffffffffu, rsum0, 1);
    rsum0 += __shfl_xor_sync(0xffffffffu, rsum0, 2);
    rsum1 += __shfl_xor_sync(0xffffffffu, rsum1, 1);
    rsum1 += __shfl_xor_sync(0xffffffffu, rsum1, 2);
    const float lsub0 = lg2(rsum0);   // e_norm = 2^(s - lsub)
    const float lsub1 = lg2(rsum1);

    // ---- drain ring, then issue K0 (BUF0) + V0 (BUF2) for sweep 2 ----
    CP_WAIT0();
    __syncthreads();
    for (int c = tid; c < 1024; c += 128) {
        const int arr = c >> 9, i = (c >> 3) & 63, ch = c & 7;
        const __half* gsrc = arr ? gV : gK;
        const unsigned dst = arr ? BUF(2) : BUF(0);
        CP16(dst + i * PITCH + ch * 16, gsrc + kvbase + (size_t)i * EE + ch * 8);
    }
    CP_COMMIT();

    if (Aout) {  // zero the strictly-upper rectangle of this q-strip
        const int c0 = q0 + TQ;
        const int w4 = (SS - c0) >> 2;
        if (w4 > 0) {
            const float4 z = make_float4(0.f, 0.f, 0.f, 0.f);
            float* Abase = Aout + ((size_t)bh * LL + q0) * SS + c0;
            for (int i = tid; i < TQ * w4; i += 128) {
                const int r = i / w4;
                const int c = i - r * w4;
                __stcs((float4*)(Abase + (size_t)r * SS + 4 * c), z);
            }
        }
    }

    float o[8][4];
#pragma unroll
    for (int nb = 0; nb < 8; ++nb)
#pragma unroll
        for (int c = 0; c < 4; ++c) o[nb][c] = 0.0f;

    // ================= sweep 2: normalized A + O =================
    for (int kt = 0; kt < nkt; ++kt) {
        const int k0 = kt * TK;
        CP_WAIT0();
        __syncthreads();
        if (kt + 1 < nkt) {  // prefetch K/V[kt+1]
            const unsigned nb1 = (kt + 1) & 1;
            const size_t rb = kvbase + (size_t)(kt + 1) * TK * EE;
            for (int c = tid; c < 1024; c += 128) {
                const int arr = c >> 9, i = (c >> 3) & 63, ch = c & 7;
                const __half* gsrc = arr ? gV : gK;
                const unsigned base = arr ? BUF(2 + nb1) : BUF(nb1);
                CP16(base + i * PITCH + ch * 16, gsrc + rb + (size_t)i * EE + ch * 8);
            }
            CP_COMMIT();
        }
        const unsigned uK = BUF(kt & 1);
        const unsigned uV = BUF(2 + (kt & 1));

        float s[8][4];
#pragma unroll
        for (int nb = 0; nb < 8; ++nb)
#pragma unroll
            for (int c = 0; c < 4; ++c) s[nb][c] = 0.0f;
#pragma unroll
        for (int ks = 0; ks < 4; ++ks) {
            unsigned qf[4];
            ldsm4(qf, uQ + qrow + ks * 32);
#pragma unroll
            for (int jg = 0; jg < 4; ++jg) {
                unsigned kf[4];
                ldsm4(kf, uK + jg * 16 * PITCH + krow + ks * 32);
                mma16816(s[2 * jg],     qf, kf[0], kf[2]);
                mma16816(s[2 * jg + 1], qf, kf[1], kf[3]);
            }
        }

        const bool anymask = (k0 + TK > gi0);
        float* A0 = Aout ? (Aout + ((size_t)bh * LL + gi0) * SS + k0) : (float*)0;
        float* A1 = Aout ? (Aout + ((size_t)bh * LL + gi1) * SS + k0) : (float*)0;

#pragma unroll
        for (int ks = 0; ks < 4; ++ks) {
            unsigned ah[4];
#pragma unroll
            for (int half = 0; half < 2; ++half) {
                const int nb = 2 * ks + half;
                const int cj = k0 + nb * 8 + 2 * tig;
                float e0 = ex2(s[nb][0] - lsub0);   // already normalized
                float e1 = ex2(s[nb][1] - lsub0);
                float e2 = ex2(s[nb][2] - lsub1);
                float e3 = ex2(s[nb][3] - lsub1);
                if (anymask) {
                    if (cj     > gi0) e0 = 0.0f;
                    if (cj + 1 > gi0) e1 = 0.0f;
                    if (cj     > gi1) e2 = 0.0f;
                    if (cj + 1 > gi1) e3 = 0.0f;
                }
                if (A0) {
                    __stcs((float2*)(A0 + nb * 8 + 2 * tig), make_float2(e0, e1));
                    __stcs((float2*)(A1 + nb * 8 + 2 * tig), make_float2(e2, e3));
                }
                ah[2 * half]     = pack2h(e0, e1);
                ah[2 * half + 1] = pack2h(e2, e3);
            }
#pragma unroll
            for (int dg = 0; dg < 4; ++dg) {
                unsigned vf[4];
                ldsm4t(vf, uV + ks * 16 * PITCH + krow + dg * 32);
                mma16816(o[2 * dg],     ah, vf[0], vf[1]);
                mma16816(o[2 * dg + 1], ah, vf[2], vf[3]);
            }
        }
    }

    if (Vout) {
        float* O0 = Vout + (((size_t)(b * LL + gi0) * HH + h) * EE);
        float* O1 = Vout + (((size_t)(b * LL + gi1) * HH + h) * EE);
#pragma unroll
        for (int nb = 0; nb < 8; ++nb) {
            *(float2*)(O0 + nb * 8 + 2 * tig) = make_float2(o[nb][0], o[nb][1]);
            *(float2*)(O1 + nb * 8 + 2 * tig) = make_float2(o[nb][2], o[nb][3]);
        }
    }
#undef BUF
}

// ---------------------------------------------------------------------------
extern "C" void kernel_launch(void* const* d_in, const int* in_sizes, int n_in,
                              void* d_out, int out_size) {
    const float* Q = (const float*)d_in[0];
    const float* K = (const float*)d_in[1];
    const float* V = (const float*)d_in[2];

    const int V_SIZE = BB * LL * HH * EE;
    const int A_SIZE = (int)((size_t)BB * HH * LL * SS);

    float* out  = (float*)d_out;
    float* Vout = 0;
    float* Aout = 0;
    if (out_size >= V_SIZE + A_SIZE) { Vout = out; Aout = out + V_SIZE; }
    else if (out_size == A_SIZE)     { Aout = out; }
    else                             { Vout = out; }

    const unsigned prep_total = 3u * (NELEM / 4);
    prep<<<(prep_total + 255u) / 256u, 256>>>(Q, K, V);

    const int smem = 46080;
    cudaFuncSetAttribute(attn_tc, cudaFuncAttributeMaxDynamicSharedMemorySize, smem);
    dim3 grid1(LL / TQ, BB * HH);
    attn_tc<<<grid1, 128, smem>>>(Aout, Vout);
}

// round 14
// speedup vs baseline: 1.1122x; 1.0122x over previous
#include <cuda_runtime.h>
#include <cuda_fp16.h>
#include <math.h>

#define BB 2
#define LL 2048
#define SS 2048
#define HH 16
#define EE 64
#define TQ 64
#define TK 64
#define PITCH 144  // smem row pitch: 64 fp16 (128B) + 16B pad

#define NELEM (BB * HH * LL * EE)

__device__ __align__(16) __half gQ[NELEM];
__device__ __align__(16) __half gK[NELEM];
__device__ __align__(16) __half gV[NELEM];

// ---------------- helpers ----------------
__device__ __forceinline__ unsigned smem_u32(const void* p) {
    unsigned a;
    asm("{ .reg .u64 t; cvta.to.shared.u64 t, %1; cvt.u32.u64 %0, t; }"
        : "=r"(a) : "l"(p));
    return a;
}
#define CP16(dst, src) \
    asm volatile("cp.async.cg.shared.global [%0], [%1], 16;" :: "r"(dst), "l"(src))
#define CP_COMMIT() asm volatile("cp.async.commit_group;" ::: "memory")
#define CP_WAIT0()  asm volatile("cp.async.wait_group 0;" ::: "memory")

__device__ __forceinline__ void ldsm4(unsigned r[4], unsigned addr) {
    asm volatile("ldmatrix.sync.aligned.m8n8.x4.shared.b16 {%0,%1,%2,%3}, [%4];"
                 : "=r"(r[0]), "=r"(r[1]), "=r"(r[2]), "=r"(r[3]) : "r"(addr));
}
__device__ __forceinline__ void ldsm4t(unsigned r[4], unsigned addr) {
    asm volatile("ldmatrix.sync.aligned.m8n8.x4.trans.shared.b16 {%0,%1,%2,%3}, [%4];"
                 : "=r"(r[0]), "=r"(r[1]), "=r"(r[2]), "=r"(r[3]) : "r"(addr));
}
__device__ __forceinline__ void mma16816(float* c, const unsigned a[4],
                                         unsigned b0, unsigned b1) {
    asm volatile(
        "mma.sync.aligned.m16n8k16.row.col.f32.f16.f16.f32 "
        "{%0,%1,%2,%3}, {%4,%5,%6,%7}, {%8,%9}, {%0,%1,%2,%3};"
        : "+f"(c[0]), "+f"(c[1]), "+f"(c[2]), "+f"(c[3])
        : "r"(a[0]), "r"(a[1]), "r"(a[2]), "r"(a[3]), "r"(b0), "r"(b1));
}
__device__ __forceinline__ unsigned pack2h(float lo, float hi) {
    __half2 p = __floats2half2_rn(lo, hi);
    return *reinterpret_cast<unsigned*>(&p);
}
__device__ __forceinline__ float ex2(float x) {
    float r;
    asm("ex2.approx.ftz.f32 %0, %1;" : "=f"(r) : "f"(x));
    return r;
}
__device__ __forceinline__ float lg2(float x) {
    float r;
    asm("lg2.approx.ftz.f32 %0, %1;" : "=f"(r) : "f"(x));
    return r;
}

// ---------------------------------------------------------------------------
// Prep: fp32 [b,s,h,e] -> fp16 [b,h,s,e]; Q scaled by 0.125*log2(e).
// ---------------------------------------------------------------------------
__global__ __launch_bounds__(256)
void prep(const float* __restrict__ Q, const float* __restrict__ K,
          const float* __restrict__ V) {
    const unsigned per = NELEM / 4;
    unsigned idx = blockIdx.x * 256u + threadIdx.x;
    if (idx >= 3u * per) return;
    const int t = idx / per;
    const unsigned c = idx % per;

    const unsigned e4 = c & 15;
    const unsigned r  = c >> 4;
    const unsigned h  = r & (HH - 1);
    const unsigned bs = r >> 4;
    const unsigned s  = bs & (LL - 1);
    const unsigned b  = bs >> 11;

    const float* src = (t == 0) ? Q : (t == 1) ? K : V;
    float4 v = *(const float4*)(src + (size_t)c * 4);
    if (t == 0) {
        const float sc = 0.18033688011112042f;  // 0.125 * log2(e)
        v.x *= sc; v.y *= sc; v.z *= sc; v.w *= sc;
    }
    __half* oh = (t == 0) ? gQ : (t == 1) ? gK : gV;
    const size_t o = (((size_t)(b * HH + h) * LL + s) * EE) + e4 * 4;
    *(uint2*)(oh + o) = make_uint2(pack2h(v.x, v.y), pack2h(v.z, v.w));
}

// ---------------------------------------------------------------------------
// Fused attention. TQ=64, 4 warps, 4 CTAs/SM.
// Sweep 1: row sums with 128-row K tiles (ring-2 of doubles), persistent Q
//          frags, fully-masked halves skipped.
// Sweep 2: recompute S, normalize via exp2(s - log2(rsum)), write A + O.
// ---------------------------------------------------------------------------
__global__ __launch_bounds__(128, 4)
void attn_tc(float* __restrict__ Aout, float* __restrict__ Vout) {
    extern __shared__ char sm[];
    const unsigned uS = smem_u32(sm);
    const unsigned uQ = uS;                               // 9216
#define BUF(i) (uS + 9216u + (unsigned)(i) * 9216u)       // 4 x 9216
#define BIG(i) (uS + 9216u + (unsigned)(i) * 18432u)      // 2 x 18432 (same mem)

    const int tid  = threadIdx.x;
    const int lane = tid & 31;
    const int w    = tid >> 5;        // 0..3
    const int g    = lane >> 2;
    const int tig  = lane & 3;

    const int bh = blockIdx.y;
    const int b  = bh / HH, h = bh % HH;
    const int qt = (int)gridDim.x - 1 - (int)blockIdx.x;  // heavy tiles first
    const int q0 = qt * TQ;

    const size_t qbase  = ((size_t)bh * LL + q0) * EE;
    const size_t kvbase = (size_t)bh * LL * EE;
    const int nkt  = qt + 1;           // 64-wide tiles (sweep 2)
    const int nbig = (qt + 2) >> 1;    // 128-wide tiles (sweep 1)

    // ---- issue Q tile + big K tile 0 (128 rows) ----
    for (int c = tid; c < 512; c += 128) {
        const int i = c >> 3, ch = c & 7;
        CP16(uQ + i * PITCH + ch * 16, gQ + qbase + (size_t)i * EE + ch * 8);
    }
    for (int c = tid; c < 1024; c += 128) {
        const int i = c >> 3, ch = c & 7;   // i in 0..127
        CP16(BIG(0) + i * PITCH + ch * 16, gK + kvbase + (size_t)i * EE + ch * 8);
    }
    CP_COMMIT();

    const int lr  = (lane & 7) + ((lane >> 3) & 1) * 8;
    const int lco = (lane >> 4) * 8;
    const unsigned qrow = (unsigned)((w * 16 + lr) * PITCH + lco * 2);
    const unsigned krow = (unsigned)(lr * PITCH + lco * 2);

    const int gi0 = q0 + w * 16 + g;
    const int gi1 = gi0 + 8;

    float rsum0 = 0.0f, rsum1 = 0.0f;
    unsigned qp[4][4];  // persistent Q frags (sweep 1)

    // ============ sweep 1: row sums, 128-row K tiles, ring-2 ============
    for (int bt = 0; bt < nbig; ++bt) {
        CP_WAIT0();
        __syncthreads();
        if (bt == 0) {
#pragma unroll
            for (int ks = 0; ks < 4; ++ks) ldsm4(qp[ks], uQ + qrow + ks * 32);
        }
        if (bt + 1 < nbig) {  // prefetch next big tile into freed slot
            const size_t rb = kvbase + (size_t)(bt + 1) * 128 * EE;
            const unsigned uN = BIG((bt + 1) & 1);
            for (int c = tid; c < 1024; c += 128) {
                const int i = c >> 3, ch = c & 7;
                CP16(uN + i * PITCH + ch * 16, gK + rb + (size_t)i * EE + ch * 8);
            }
            CP_COMMIT();
        }
        const unsigned uKbig = BIG(bt & 1);

#pragma unroll
        for (int half = 0; half < 2; ++half) {
            const int k0 = bt * 128 + half * 64;
            if (k0 > q0 + TQ - 1) break;      // entire half beyond causal limit
            const unsigned uK = uKbig + (unsigned)half * 64u * PITCH;

            float s[8][4];
#pragma unroll
            for (int nb = 0; nb < 8; ++nb)
#pragma unroll
                for (int c = 0; c < 4; ++c) s[nb][c] = 0.0f;
#pragma unroll
            for (int ks = 0; ks < 4; ++ks) {
#pragma unroll
                for (int jg = 0; jg < 4; ++jg) {
                    unsigned kf[4];
                    ldsm4(kf, uK + jg * 16 * PITCH + krow + ks * 32);
                    mma16816(s[2 * jg],     qp[ks], kf[0], kf[2]);
                    mma16816(s[2 * jg + 1], qp[ks], kf[1], kf[3]);
                }
            }
            const bool anymask = (k0 + TK > gi0);
#pragma unroll
            for (int nb = 0; nb < 8; ++nb) {
                const int cj = k0 + nb * 8 + 2 * tig;
                float e0 = ex2(s[nb][0]);
                float e1 = ex2(s[nb][1]);
                float e2 = ex2(s[nb][2]);
                float e3 = ex2(s[nb][3]);
                if (anymask) {
                    if (cj     > gi0) e0 = 0.0f;
                    if (cj + 1 > gi0) e1 = 0.0f;
                    if (cj     > gi1) e2 = 0.0f;
                    if (cj + 1 > gi1) e3 = 0.0f;
                }
                rsum0 += e0 + e1;
                rsum1 += e2 + e3;
            }
        }
    }

    rsum0 += __shfl_xor_sync(0xffffffffu, rsum0, 1);
    rsum0 += __shfl_xor_sync(0xffffffffu, rsum0, 2);
    rsum1 += __shfl_xor_sync(0xffffffffu, rsum1, 1);
    rsum1 += __shfl_xor_sync(0xffffffffu, rsum1, 2);
    const float lsub0 = lg2(rsum0);   // e_norm = 2^(s - lsub)
    const float lsub1 = lg2(rsum1);

    // ---- issue K0 (BUF0) + V0 (BUF2) for sweep 2 ----
    __syncthreads();   // everyone done reading sweep-1 tiles
    for (int c = tid; c < 1024; c += 128) {
        const int arr = c >> 9, i = (c >> 3) & 63, ch = c & 7;
        const __half* gsrc = arr ? gV : gK;
        const unsigned dst = arr ? BUF(2) : BUF(0);
        CP16(dst + i * PITCH + ch * 16, gsrc + kvbase + (size_t)i * EE + ch * 8);
    }
    CP_COMMIT();

    if (Aout) {  // zero the strictly-upper rectangle of this q-strip
        const int c0 = q0 + TQ;
        const int w4 = (SS - c0) >> 2;
        if (w4 > 0) {
            const float4 z = make_float4(0.f, 0.f, 0.f, 0.f);
            float* Abase = Aout + ((size_t)bh * LL + q0) * SS + c0;
            for (int i = tid; i < TQ * w4; i += 128) {
                const int r = i / w4;
                const int c = i - r * w4;
                __stcs((float4*)(Abase + (size_t)r * SS + 4 * c), z);
            }
        }
    }

    float o[8][4];
#pragma unroll
    for (int nb = 0; nb < 8; ++nb)
#pragma unroll
        for (int c = 0; c < 4; ++c) o[nb][c] = 0.0f;

    // ================= sweep 2: normalized A + O =================
    for (int kt = 0; kt < nkt; ++kt) {
        const int k0 = kt * TK;
        CP_WAIT0();
        __syncthreads();
        if (kt + 1 < nkt) {  // prefetch K/V[kt+1]
            const unsigned nb1 = (kt + 1) & 1;
            const size_t rb = kvbase + (size_t)(kt + 1) * TK * EE;
            for (int c = tid; c < 1024; c += 128) {
                const int arr = c >> 9, i = (c >> 3) & 63, ch = c & 7;
                const __half* gsrc = arr ? gV : gK;
                const unsigned base = arr ? BUF(2 + nb1) : BUF(nb1);
                CP16(base + i * PITCH + ch * 16, gsrc + rb + (size_t)i * EE + ch * 8);
            }
            CP_COMMIT();
        }
        const unsigned uK = BUF(kt & 1);
        const unsigned uV = BUF(2 + (kt & 1));

        float s[8][4];
#pragma unroll
        for (int nb = 0; nb < 8; ++nb)
#pragma unroll
            for (int c = 0; c < 4; ++c) s[nb][c] = 0.0f;
#pragma unroll
        for (int ks = 0; ks < 4; ++ks) {
            unsigned qf[4];
            ldsm4(qf, uQ + qrow + ks * 32);
#pragma unroll
            for (int jg = 0; jg < 4; ++jg) {
                unsigned kf[4];
                ldsm4(kf, uK + jg * 16 * PITCH + krow + ks * 32);
                mma16816(s[2 * jg],     qf, kf[0], kf[2]);
                mma16816(s[2 * jg + 1], qf, kf[1], kf[3]);
            }
        }

        const bool anymask = (k0 + TK > gi0);
        float* A0 = Aout ? (Aout + ((size_t)bh * LL + gi0) * SS + k0) : (float*)0;
        float* A1 = Aout ? (Aout + ((size_t)bh * LL + gi1) * SS + k0) : (float*)0;

#pragma unroll
        for (int ks = 0; ks < 4; ++ks) {
            unsigned ah[4];
#pragma unroll
            for (int half = 0; half < 2; ++half) {
                const int nb = 2 * ks + half;
                const int cj = k0 + nb * 8 + 2 * tig;
                float e0 = ex2(s[nb][0] - lsub0);   // already normalized
                float e1 = ex2(s[nb][1] - lsub0);
                float e2 = ex2(s[nb][2] - lsub1);
                float e3 = ex2(s[nb][3] - lsub1);
                if (anymask) {
                    if (cj     > gi0) e0 = 0.0f;
                    if (cj + 1 > gi0) e1 = 0.0f;
                    if (cj     > gi1) e2 = 0.0f;
                    if (cj + 1 > gi1) e3 = 0.0f;
                }
                if (A0) {
                    __stcs((float2*)(A0 + nb * 8 + 2 * tig), make_float2(e0, e1));
                    __stcs((float2*)(A1 + nb * 8 + 2 * tig), make_float2(e2, e3));
                }
                ah[2 * half]     = pack2h(e0, e1);
                ah[2 * half + 1] = pack2h(e2, e3);
            }
#pragma unroll
            for (int dg = 0; dg < 4; ++dg) {
                unsigned vf[4];
                ldsm4t(vf, uV + ks * 16 * PITCH + krow + dg * 32);
                mma16816(o[2 * dg],     ah, vf[0], vf[1]);
                mma16816(o[2 * dg + 1], ah, vf[2], vf[3]);
            }
        }
    }

    if (Vout) {
        float* O0 = Vout + (((size_t)(b * LL + gi0) * HH + h) * EE);
        float* O1 = Vout + (((size_t)(b * LL + gi1) * HH + h) * EE);
#pragma unroll
        for (int nb = 0; nb < 8; ++nb) {
            *(float2*)(O0 + nb * 8 + 2 * tig) = make_float2(o[nb][0], o[nb][1]);
            *(float2*)(O1 + nb * 8 + 2 * tig) = make_float2(o[nb][2], o[nb][3]);
        }
    }
#undef BUF
#undef BIG
}

// ---------------------------------------------------------------------------
extern "C" void kernel_launch(void* const* d_in, const int* in_sizes, int n_in,
                              void* d_out, int out_size) {
    const float* Q = (const float*)d_in[0];
    const float* K = (const float*)d_in[1];
    const float* V = (const float*)d_in[2];

    const int V_SIZE = BB * LL * HH * EE;
    const int A_SIZE = (int)((size_t)BB * HH * LL * SS);

    float* out  = (float*)d_out;
    float* Vout = 0;
    float* Aout = 0;
    if (out_size >= V_SIZE + A_SIZE) { Vout = out; Aout = out + V_SIZE; }
    else if (out_size == A_SIZE)     { Aout = out; }
    else                             { Vout = out; }

    const unsigned prep_total = 3u * (NELEM / 4);
    prep<<<(prep_total + 255u) / 256u, 256>>>(Q, K, V);

    const int smem = 46080;
    cudaFuncSetAttribute(attn_tc, cudaFuncAttributeMaxDynamicSharedMemorySize, smem);
    dim3 grid1(LL / TQ, BB * HH);
    attn_tc<<<grid1, 128, smem>>>(Aout, Vout);
}

// round 15
// speedup vs baseline: 1.1501x; 1.0341x over previous
#include <cuda_runtime.h>
#include <cuda_fp16.h>
#include <math.h>

#define BB 2
#define LL 2048
#define SS 2048
#define HH 16
#define EE 64
#define TQ 64
#define TK 64

#define NELEM (BB * HH * LL * EE)

__device__ __align__(16) __half gQ[NELEM];
__device__ __align__(16) __half gK[NELEM];
__device__ __align__(16) __half gV[NELEM];

// ---------------- helpers ----------------
__device__ __forceinline__ unsigned smem_u32(const void* p) {
    unsigned a;
    asm("{ .reg .u64 t; cvta.to.shared.u64 t, %1; cvt.u32.u64 %0, t; }"
        : "=r"(a) : "l"(p));
    return a;
}
#define CP16(dst, src) \
    asm volatile("cp.async.cg.shared.global [%0], [%1], 16;" :: "r"(dst), "l"(src))
#define CP_COMMIT() asm volatile("cp.async.commit_group;" ::: "memory")
#define CP_WAIT0()  asm volatile("cp.async.wait_group 0;" ::: "memory")
#define CP_WAIT1()  asm volatile("cp.async.wait_group 1;" ::: "memory")

__device__ __forceinline__ void ldsm4(unsigned r[4], unsigned addr) {
    asm volatile("ldmatrix.sync.aligned.m8n8.x4.shared.b16 {%0,%1,%2,%3}, [%4];"
                 : "=r"(r[0]), "=r"(r[1]), "=r"(r[2]), "=r"(r[3]) : "r"(addr));
}
__device__ __forceinline__ void ldsm4t(unsigned r[4], unsigned addr) {
    asm volatile("ldmatrix.sync.aligned.m8n8.x4.trans.shared.b16 {%0,%1,%2,%3}, [%4];"
                 : "=r"(r[0]), "=r"(r[1]), "=r"(r[2]), "=r"(r[3]) : "r"(addr));
}
__device__ __forceinline__ void mma16816(float* c, const unsigned a[4],
                                         unsigned b0, unsigned b1) {
    asm volatile(
        "mma.sync.aligned.m16n8k16.row.col.f32.f16.f16.f32 "
        "{%0,%1,%2,%3}, {%4,%5,%6,%7}, {%8,%9}, {%0,%1,%2,%3};"
        : "+f"(c[0]), "+f"(c[1]), "+f"(c[2]), "+f"(c[3])
        : "r"(a[0]), "r"(a[1]), "r"(a[2]), "r"(a[3]), "r"(b0), "r"(b1));
}
__device__ __forceinline__ unsigned pack2h(float lo, float hi) {
    __half2 p = __floats2half2_rn(lo, hi);
    return *reinterpret_cast<unsigned*>(&p);
}
__device__ __forceinline__ float ex2(float x) {
    float r;
    asm("ex2.approx.ftz.f32 %0, %1;" : "=f"(r) : "f"(x));
    return r;
}
__device__ __forceinline__ float lg2(float x) {
    float r;
    asm("lg2.approx.ftz.f32 %0, %1;" : "=f"(r) : "f"(x));
    return r;
}

// ---------------------------------------------------------------------------
// Prep: fp32 [b,s,h,e] -> fp16 [b,h,s,e]; Q scaled by 0.125*log2(e).
// ---------------------------------------------------------------------------
__global__ __launch_bounds__(256)
void prep(const float* __restrict__ Q, const float* __restrict__ K,
          const float* __restrict__ V) {
    const unsigned per = NELEM / 4;
    unsigned idx = blockIdx.x * 256u + threadIdx.x;
    if (idx >= 3u * per) return;
    const int t = idx / per;
    const unsigned c = idx % per;

    const unsigned e4 = c & 15;
    const unsigned r  = c >> 4;
    const unsigned h  = r & (HH - 1);
    const unsigned bs = r >> 4;
    const unsigned s  = bs & (LL - 1);
    const unsigned b  = bs >> 11;

    const float* src = (t == 0) ? Q : (t == 1) ? K : V;
    float4 v = *(const float4*)(src + (size_t)c * 4);
    if (t == 0) {
        const float sc = 0.18033688011112042f;  // 0.125 * log2(e)
        v.x *= sc; v.y *= sc; v.z *= sc; v.w *= sc;
    }
    __half* oh = (t == 0) ? gQ : (t == 1) ? gK : gV;
    const size_t o = (((size_t)(b * HH + h) * LL + s) * EE) + e4 * 4;
    *(uint2*)(oh + o) = make_uint2(pack2h(v.x, v.y), pack2h(v.z, v.w));
}

// ---------------------------------------------------------------------------
// Fused attention. TQ=64, 4 warps, 4 CTAs/SM. 128B-pitch XOR-swizzled smem.
// Sweep 1: row sums, 128-row K tiles, ring-3 (prefetch distance 2).
// Sweep 2: ring-3 K + ring-3 V 64-wide (distance 2); exp2(s - lg2(rsum)).
// ---------------------------------------------------------------------------
__global__ __launch_bounds__(128, 4)
void attn_tc(float* __restrict__ Aout, float* __restrict__ Vout) {
    extern __shared__ char sm[];
    const unsigned uS = smem_u32(sm);
    const unsigned uQ = uS;                               // 64 x 128 = 8192
#define BIG(i)  (uS + 8192u + (unsigned)(i) * 16384u)     // 3 x 16384 (sweep 1)
#define KS2(i)  (uS + 8192u + (unsigned)(i) * 8192u)      // slots 0..2 (sweep 2 K)
#define VS2(i)  (uS + 32768u + (unsigned)(i) * 8192u)     // slots 3..5 (sweep 2 V)

    const int tid  = threadIdx.x;
    const int lane = tid & 31;
    const int w    = tid >> 5;        // 0..3
    const int g    = lane >> 2;
    const int tig  = lane & 3;

    const int bh = blockIdx.y;
    const int b  = bh / HH, h = bh % HH;
    const int qt = (int)gridDim.x - 1 - (int)blockIdx.x;  // heavy tiles first
    const int q0 = qt * TQ;

    const size_t qbase  = ((size_t)bh * LL + q0) * EE;
    const size_t kvbase = (size_t)bh * LL * EE;
    const int nkt  = qt + 1;           // 64-wide tiles (sweep 2)
    const int nbig = (qt + 2) >> 1;    // 128-wide tiles (sweep 1)

    // per-thread store swizzle: chunk (i, ch) -> i*128 + (ch*16 ^ ((i&7)<<4))
    // with c += 128 stride: i&7 and ch are thread-constant.
    const unsigned st_sw = ((((unsigned)tid >> 3) & 7u) << 4);
    const unsigned st_ch = ((unsigned)tid & 7u) * 16u;
    const unsigned st_co = st_ch ^ st_sw;   // swizzled column byte offset

    // ---- issue Q tile + big K tiles 0,1 ----
    for (int c = tid; c < 512; c += 128) {
        const int i = c >> 3;
        CP16(uQ + i * 128 + st_co, gQ + qbase + (size_t)i * EE + (st_ch >> 1));
    }
    CP_COMMIT();
    for (int p = 0; p < 2; ++p) {
        if (p < nbig) {
            const size_t rb = kvbase + (size_t)p * 128 * EE;
            for (int c = tid; c < 1024; c += 128) {
                const int i = c >> 3;
                CP16(BIG(p) + i * 128 + st_co, gK + rb + (size_t)i * EE + (st_ch >> 1));
            }
        }
        CP_COMMIT();
    }

    const int lr  = (lane & 7) + ((lane >> 3) & 1) * 8;
    const int lco = (lane >> 4) * 8;
    const unsigned rd_sw = (((unsigned)lr & 7u) << 4);    // lane-constant swizzle
    // column byte offsets for the 4 k-chunks, pre-swizzled:
    unsigned colq[4];
#pragma unroll
    for (int ks = 0; ks < 4; ++ks) colq[ks] = ((unsigned)(lco * 2 + ks * 32)) ^ rd_sw;
    const unsigned qrowb = (unsigned)((w * 16 + lr) * 128);
    const unsigned krowb = (unsigned)(lr * 128);

    const int gi0 = q0 + w * 16 + g;
    const int gi1 = gi0 + 8;

    float rsum0 = 0.0f, rsum1 = 0.0f;
    unsigned qp[4][4];  // persistent Q frags (sweep 1)

    // ============ sweep 1: row sums, 128-row K tiles, ring-3 ============
    for (int bt = 0; bt < nbig; ++bt) {
        CP_WAIT1();           // Q + tiles <= bt complete (<=1 newer pending)
        __syncthreads();
        if (bt == 0) {
#pragma unroll
            for (int ks = 0; ks < 4; ++ks) ldsm4(qp[ks], uQ + qrowb + colq[ks]);
        }
        if (bt + 2 < nbig) {  // issue big K(bt+2) into slot freed at bt-1
            const size_t rb = kvbase + (size_t)(bt + 2) * 128 * EE;
            const unsigned uN = BIG((bt + 2) % 3);
            for (int c = tid; c < 1024; c += 128) {
                const int i = c >> 3;
                CP16(uN + i * 128 + st_co, gK + rb + (size_t)i * EE + (st_ch >> 1));
            }
        }
        CP_COMMIT();
        const unsigned uKbig = BIG(bt % 3);

#pragma unroll
        for (int half = 0; half < 2; ++half) {
            const int k0 = bt * 128 + half * 64;
            if (k0 > q0 + TQ - 1) break;      // entire half beyond causal limit
            const unsigned uK = uKbig + (unsigned)half * 64u * 128u;

            float s[8][4];
#pragma unroll
            for (int nb = 0; nb < 8; ++nb)
#pragma unroll
                for (int c = 0; c < 4; ++c) s[nb][c] = 0.0f;
#pragma unroll
            for (int ks = 0; ks < 4; ++ks) {
#pragma unroll
                for (int jg = 0; jg < 4; ++jg) {
                    unsigned kf[4];
                    ldsm4(kf, uK + jg * 16 * 128 + krowb + colq[ks]);
                    mma16816(s[2 * jg],     qp[ks], kf[0], kf[2]);
                    mma16816(s[2 * jg + 1], qp[ks], kf[1], kf[3]);
                }
            }
            const bool anymask = (k0 + TK > gi0);
#pragma unroll
            for (int nb = 0; nb < 8; ++nb) {
                const int cj = k0 + nb * 8 + 2 * tig;
                float e0 = ex2(s[nb][0]);
                float e1 = ex2(s[nb][1]);
                float e2 = ex2(s[nb][2]);
                float e3 = ex2(s[nb][3]);
                if (anymask) {
                    if (cj     > gi0) e0 = 0.0f;
                    if (cj + 1 > gi0) e1 = 0.0f;
                    if (cj     > gi1) e2 = 0.0f;
                    if (cj + 1 > gi1) e3 = 0.0f;
                }
                rsum0 += e0 + e1;
                rsum1 += e2 + e3;
            }
        }
    }

    rsum0 += __shfl_xor_sync(0xffffffffu, rsum0, 1);
    rsum0 += __shfl_xor_sync(0xffffffffu, rsum0, 2);
    rsum1 += __shfl_xor_sync(0xffffffffu, rsum1, 1);
    rsum1 += __shfl_xor_sync(0xffffffffu, rsum1, 2);
    const float lsub0 = lg2(rsum0);   // e_norm = 2^(s - lsub)
    const float lsub1 = lg2(rsum1);

    // ---- drain, then pre-issue (K,V) pairs 0 and 1 for sweep 2 ----
    CP_WAIT0();
    __syncthreads();
    for (int p = 0; p < 2; ++p) {
        if (p < nkt) {
            const size_t rb = kvbase + (size_t)p * TK * EE;
            for (int c = tid; c < 1024; c += 128) {
                const int arr = c >> 9, i = (c >> 3) & 63;
                const __half* gsrc = arr ? gV : gK;
                const unsigned dst = arr ? VS2(p) : KS2(p);
                CP16(dst + i * 128 + st_co, gsrc + rb + (size_t)i * EE + (st_ch >> 1));
            }
        }
        CP_COMMIT();
    }

    if (Aout) {  // zero the strictly-upper rectangle of this q-strip
        const int c0 = q0 + TQ;
        const int w4 = (SS - c0) >> 2;
        if (w4 > 0) {
            const float4 z = make_float4(0.f, 0.f, 0.f, 0.f);
            float* Abase = Aout + ((size_t)bh * LL + q0) * SS + c0;
            for (int i = tid; i < TQ * w4; i += 128) {
                const int r = i / w4;
                const int c = i - r * w4;
                __stcs((float4*)(Abase + (size_t)r * SS + 4 * c), z);
            }
        }
    }

    float o[8][4];
#pragma unroll
    for (int nb = 0; nb < 8; ++nb)
#pragma unroll
        for (int c = 0; c < 4; ++c) o[nb][c] = 0.0f;

    // ================= sweep 2: normalized A + O (ring-3, distance 2) =======
    for (int kt = 0; kt < nkt; ++kt) {
        const int k0 = kt * TK;
        CP_WAIT1();           // pair kt complete (<=1 newer pending)
        __syncthreads();
        if (kt + 2 < nkt) {   // issue pair kt+2 into slot freed at kt-1
            const int sl = (kt + 2) % 3;
            const size_t rb = kvbase + (size_t)(kt + 2) * TK * EE;
            for (int c = tid; c < 1024; c += 128) {
                const int arr = c >> 9, i = (c >> 3) & 63;
                const __half* gsrc = arr ? gV : gK;
                const unsigned dst = arr ? VS2(sl) : KS2(sl);
                CP16(dst + i * 128 + st_co, gsrc + rb + (size_t)i * EE + (st_ch >> 1));
            }
        }
        CP_COMMIT();
        const unsigned uK = KS2(kt % 3);
        const unsigned uV = VS2(kt % 3);

        float s[8][4];
#pragma unroll
        for (int nb = 0; nb < 8; ++nb)
#pragma unroll
            for (int c = 0; c < 4; ++c) s[nb][c] = 0.0f;
#pragma unroll
        for (int ks = 0; ks < 4; ++ks) {
            unsigned qf[4];
            ldsm4(qf, uQ + qrowb + colq[ks]);
#pragma unroll
            for (int jg = 0; jg < 4; ++jg) {
                unsigned kf[4];
                ldsm4(kf, uK + jg * 16 * 128 + krowb + colq[ks]);
                mma16816(s[2 * jg],     qf, kf[0], kf[2]);
                mma16816(s[2 * jg + 1], qf, kf[1], kf[3]);
            }
        }

        const bool anymask = (k0 + TK > gi0);
        float* A0 = Aout ? (Aout + ((size_t)bh * LL + gi0) * SS + k0) : (float*)0;
        float* A1 = Aout ? (Aout + ((size_t)bh * LL + gi1) * SS + k0) : (float*)0;

#pragma unroll
        for (int ks = 0; ks < 4; ++ks) {
            unsigned ah[4];
#pragma unroll
            for (int half = 0; half < 2; ++half) {
                const int nb = 2 * ks + half;
                const int cj = k0 + nb * 8 + 2 * tig;
                float e0 = ex2(s[nb][0] - lsub0);   // already normalized
                float e1 = ex2(s[nb][1] - lsub0);
                float e2 = ex2(s[nb][2] - lsub1);
                float e3 = ex2(s[nb][3] - lsub1);
                if (anymask) {
                    if (cj     > gi0) e0 = 0.0f;
                    if (cj + 1 > gi0) e1 = 0.0f;
                    if (cj     > gi1) e2 = 0.0f;
                    if (cj + 1 > gi1) e3 = 0.0f;
                }
                if (A0) {
                    __stcs((float2*)(A0 + nb * 8 + 2 * tig), make_float2(e0, e1));
                    __stcs((float2*)(A1 + nb * 8 + 2 * tig), make_float2(e2, e3));
                }
                ah[2 * half]     = pack2h(e0, e1);
                ah[2 * half + 1] = pack2h(e2, e3);
            }
#pragma unroll
            for (int dg = 0; dg < 4; ++dg) {
                unsigned vf[4];
                ldsm4t(vf, uV + ks * 16 * 128 + krowb +
                           (((unsigned)(lco * 2 + dg * 32)) ^ rd_sw));
                mma16816(o[2 * dg],     ah, vf[0], vf[1]);
                mma16816(o[2 * dg + 1], ah, vf[2], vf[3]);
            }
        }
    }

    if (Vout) {
        float* O0 = Vout + (((size_t)(b * LL + gi0) * HH + h) * EE);
        float* O1 = Vout + (((size_t)(b * LL + gi1) * HH + h) * EE);
#pragma unroll
        for (int nb = 0; nb < 8; ++nb) {
            *(float2*)(O0 + nb * 8 + 2 * tig) = make_float2(o[nb][0], o[nb][1]);
            *(float2*)(O1 + nb * 8 + 2 * tig) = make_float2(o[nb][2], o[nb][3]);
        }
    }
#undef BIG
#undef KS2
#undef VS2
}

// ---------------------------------------------------------------------------
extern "C" void kernel_launch(void* const* d_in, const int* in_sizes, int n_in,
                              void* d_out, int out_size) {
    const float* Q = (const float*)d_in[0];
    const float* K = (const float*)d_in[1];
    const float* V = (const float*)d_in[2];

    const int V_SIZE = BB * LL * HH * EE;
    const int A_SIZE = (int)((size_t)BB * HH * LL * SS);

    float* out  = (float*)d_out;
    float* Vout = 0;
    float* Aout = 0;
    if (out_size >= V_SIZE + A_SIZE) { Vout = out; Aout = out + V_SIZE; }
    else if (out_size == A_SIZE)     { Aout = out; }
    else                             { Vout = out; }

    const unsigned prep_total = 3u * (NELEM / 4);
    prep<<<(prep_total + 255u) / 256u, 256>>>(Q, K, V);

    const int smem = 57344;
    cudaFuncSetAttribute(attn_tc, cudaFuncAttributeMaxDynamicSharedMemorySize, smem);
    dim3 grid1(LL / TQ, BB * HH);
    attn_tc<<<grid1, 128, smem>>>(Aout, Vout);
}